// round 12
// baseline (speedup 1.0000x reference)
#include <cuda_runtime.h>
#include <cuda_bf16.h>
#include <cuda_fp16.h>
#include <cstdint>

#define NB   4
#define CIN  128
#define NTOT 2048
#define NH   4
#define HD   64
#define OUTC 256
#define NP   16
#define NITER 16           // 2048 / 128-row j-chunks

// ---------------- scratch ----------------
__device__ __half g_x[NB * NTOT * CIN];                // scattered input fp16 (b,n,c)
__device__ __nv_bfloat16 g_ph[NB * NTOT * CIN];        // pcd_up hi (b,n,c)
__device__ __nv_bfloat16 g_pl[NB * NTOT * CIN];        // pcd_up lo
__device__ __half g_q[NP * NTOT * HD];                 // (p,n,d) fp16, pre-scaled 1/8
__device__ __half g_k[NP * NTOT * HD];                 // (p,n,d) fp16
__device__ __half g_v[NP * NTOT * HD];                 // (p,n,d) fp16

// ---------------- helpers ----------------
__device__ __forceinline__ uint32_t smem_u32(const void* p) {
    uint32_t a;
    asm("{ .reg .u64 t; cvta.to.shared.u64 t, %1; cvt.u32.u64 %0, t; }" : "=r"(a) : "l"(p));
    return a;
}
__device__ __forceinline__ void ldsm_x4(uint32_t& r0, uint32_t& r1, uint32_t& r2, uint32_t& r3,
                                        uint32_t addr) {
    asm volatile("ldmatrix.sync.aligned.m8n8.x4.shared.b16 {%0,%1,%2,%3}, [%4];"
                 : "=r"(r0), "=r"(r1), "=r"(r2), "=r"(r3) : "r"(addr));
}
__device__ __forceinline__ void ldsm_x4_t(uint32_t& r0, uint32_t& r1, uint32_t& r2, uint32_t& r3,
                                          uint32_t addr) {
    asm volatile("ldmatrix.sync.aligned.m8n8.x4.trans.shared.b16 {%0,%1,%2,%3}, [%4];"
                 : "=r"(r0), "=r"(r1), "=r"(r2), "=r"(r3) : "r"(addr));
}
__device__ __forceinline__ void mma16816(float* d, const uint32_t* a, uint32_t b0, uint32_t b1) {
    asm volatile("mma.sync.aligned.m16n8k16.row.col.f32.bf16.bf16.f32 "
                 "{%0,%1,%2,%3}, {%4,%5,%6,%7}, {%8,%9}, {%0,%1,%2,%3};"
                 : "+f"(d[0]), "+f"(d[1]), "+f"(d[2]), "+f"(d[3])
                 : "r"(a[0]), "r"(a[1]), "r"(a[2]), "r"(a[3]), "r"(b0), "r"(b1));
}
__device__ __forceinline__ void mma16816h(float* d, const uint32_t* a, uint32_t b0, uint32_t b1) {
    asm volatile("mma.sync.aligned.m16n8k16.row.col.f32.f16.f16.f32 "
                 "{%0,%1,%2,%3}, {%4,%5,%6,%7}, {%8,%9}, {%0,%1,%2,%3};"
                 : "+f"(d[0]), "+f"(d[1]), "+f"(d[2]), "+f"(d[3])
                 : "r"(a[0]), "r"(a[1]), "r"(a[2]), "r"(a[3]), "r"(b0), "r"(b1));
}
#define CP16(dst, src) asm volatile("cp.async.cg.shared.global [%0], [%1], 16;" :: "r"(dst), "l"(src))
#define CP_COMMIT()    asm volatile("cp.async.commit_group;" ::: "memory")
#define CP_WAIT(n)     asm volatile("cp.async.wait_group %0;" :: "n"(n) : "memory")

__device__ __forceinline__ void split_bf16(float x, __nv_bfloat16& hi, __nv_bfloat16& lo) {
    hi = __float2bfloat16(x);
    lo = __float2bfloat16(x - __bfloat162float(hi));
}

// ============================================================
// K1: tiled transpose + scatter
// ============================================================
__global__ __launch_bounds__(256) void prep_kernel(
    const float* __restrict__ sel, const float* __restrict__ drp,
    const int* __restrict__ isel, const int* __restrict__ idrp,
    const float* __restrict__ pcd)
{
    __shared__ float S[128][33];
    __shared__ int dsts[32];
    int tx = blockIdx.x, mode = blockIdx.y, b = blockIdx.z;
    int t = threadIdx.x;

    if (mode == 0) {
        const float* src; const int* ip; int n0;
        if (tx < 32) { src = sel + (size_t)b * CIN * 1024; ip = isel; n0 = tx * 32; }
        else         { src = drp + (size_t)b * CIN * 1024; ip = idrp; n0 = tx * 32 - 1024; }
        #pragma unroll
        for (int i = 0; i < 16; ++i) {
            int idx = t + i * 256;
            int c = idx >> 5, n = idx & 31;
            S[c][n] = src[(size_t)c * 1024 + n0 + n];
        }
        if (t < 32) dsts[t] = ip[b * 1024 + n0 + t];
    } else {
        int n0 = tx * 32;
        #pragma unroll
        for (int i = 0; i < 16; ++i) {
            int idx = t + i * 256;
            int c = idx >> 5, n = idx & 31;
            S[c][n] = pcd[((size_t)b * CIN + c) * NTOT + n0 + n];
        }
        if (t < 32) dsts[t] = n0 + t;
    }
    __syncthreads();

    int n = t >> 3, cs = (t & 7) * 16;
    int dst = dsts[n];
    if (mode == 0) {
        __half* dx = g_x + ((size_t)(b * NTOT + dst)) * CIN + cs;
        __align__(16) __half hb[16];
        #pragma unroll
        for (int i = 0; i < 16; ++i) hb[i] = __float2half_rn(S[cs + i][n]);
        *(uint4*)dx       = *(uint4*)hb;
        *(uint4*)(dx + 8) = *(uint4*)(hb + 8);
    } else {
        __nv_bfloat16* dh = g_ph + ((size_t)(b * NTOT + dst)) * CIN + cs;
        __nv_bfloat16* dl = g_pl + ((size_t)(b * NTOT + dst)) * CIN + cs;
        __align__(16) __nv_bfloat16 hb[16], lb[16];
        #pragma unroll
        for (int i = 0; i < 16; ++i) split_bf16(S[cs + i][n], hb[i], lb[i]);
        *(uint4*)dh       = *(uint4*)hb;
        *(uint4*)(dh + 8) = *(uint4*)(hb + 8);
        *(uint4*)dl       = *(uint4*)lb;
        *(uint4*)(dl + 8) = *(uint4*)(lb + 8);
    }
}

// ============================================================
// K2: projections on tensor cores
//     m<3 (q/k/v): single-term fp16; m=3 (skip): 3-term bf16
// ============================================================
#define PW  0
#define PX  17408
#define PWH 0
#define PWL 17408
#define PXH 34816
#define PXL 69632
#define SMEM_PROJ 104448

__global__ __launch_bounds__(256, 2) void proj_kernel(
    const float* __restrict__ Wq, const float* __restrict__ Wk,
    const float* __restrict__ Wv, const float* __restrict__ Wskip,
    float* __restrict__ out)
{
    extern __shared__ __align__(1024) char smem[];
    uint32_t sb = smem_u32(smem);
    int tid = threadIdx.x, wid = tid >> 5, lane = tid & 31;
    int nb = blockIdx.x, ob = blockIdx.y, b = blockIdx.z;
    int m = ob >> 2, h = ob & 3;
    int p = b * NH + h;
    int mw = wid & 3, nw = wid >> 2;
    float acc[8][4] = {};

    if (m < 3) {
        const float* W = (m == 0 ? Wq : m == 1 ? Wk : Wv) + h * 64 * CIN;
        const __half* X = g_x + ((size_t)b * NTOT + nb * 128) * CIN;

        #pragma unroll
        for (int l = 0; l < 8; ++l) {
            int idx = tid + l * 256;
            int o = idx >> 5, c4 = (idx & 31) * 4;
            float4 w = *(const float4*)(W + o * 128 + c4);
            __align__(8) __half hw[4] = {
                __float2half_rn(w.x), __float2half_rn(w.y),
                __float2half_rn(w.z), __float2half_rn(w.w) };
            *(uint2*)(smem + PW + o * 272 + c4 * 2) = *(uint2*)hw;
        }
        #pragma unroll
        for (int l = 0; l < 8; ++l) {
            int idx = tid + l * 256;
            int n = idx >> 4, u = idx & 15;
            *(uint4*)(smem + PX + n * 272 + u * 16) = ((const uint4*)(X + (size_t)n * CIN))[u];
        }
        __syncthreads();

        uint32_t wa = sb + PW + (mw * 16 + (lane & 15)) * 272 + (lane >> 4) * 16;
        uint32_t xb = sb + PX + (((lane & 7) | ((lane & 16) >> 1)) + nw * 64) * 272
                    + ((lane >> 3) & 1) * 16;
        #pragma unroll
        for (int kt = 0; kt < 8; ++kt) {
            uint32_t ah[4];
            ldsm_x4(ah[0], ah[1], ah[2], ah[3], wa + kt * 32);
            #pragma unroll
            for (int nt = 0; nt < 4; ++nt) {
                uint32_t bh[4];
                ldsm_x4(bh[0], bh[1], bh[2], bh[3], xb + nt * (16 * 272) + kt * 32);
                mma16816h(acc[2 * nt],     ah, bh[0], bh[1]);
                mma16816h(acc[2 * nt + 1], ah, bh[2], bh[3]);
            }
        }
    } else {
        const float* W = Wskip + h * 64 * CIN;
        const __nv_bfloat16* Xh = g_ph + ((size_t)b * NTOT + nb * 128) * CIN;
        const __nv_bfloat16* Xl = g_pl + ((size_t)b * NTOT + nb * 128) * CIN;

        #pragma unroll
        for (int l = 0; l < 8; ++l) {
            int idx = tid + l * 256;
            int o = idx >> 5, c4 = (idx & 31) * 4;
            float4 w = *(const float4*)(W + o * 128 + c4);
            __nv_bfloat16 h0, h1, h2, h3, l0, l1, l2, l3;
            split_bf16(w.x, h0, l0); split_bf16(w.y, h1, l1);
            split_bf16(w.z, h2, l2); split_bf16(w.w, h3, l3);
            __nv_bfloat162* dh = (__nv_bfloat162*)(smem + PWH + o * 272 + c4 * 2);
            __nv_bfloat162* dl = (__nv_bfloat162*)(smem + PWL + o * 272 + c4 * 2);
            dh[0] = {h0, h1}; dh[1] = {h2, h3};
            dl[0] = {l0, l1}; dl[1] = {l2, l3};
        }
        #pragma unroll
        for (int l = 0; l < 8; ++l) {
            int idx = tid + l * 256;
            int n = idx >> 4, u = idx & 15;
            *(uint4*)(smem + PXH + n * 272 + u * 16) = ((const uint4*)(Xh + (size_t)n * CIN))[u];
            *(uint4*)(smem + PXL + n * 272 + u * 16) = ((const uint4*)(Xl + (size_t)n * CIN))[u];
        }
        __syncthreads();

        uint32_t wa = sb + PWH + (mw * 16 + (lane & 15)) * 272 + (lane >> 4) * 16;
        uint32_t xb = sb + PXH + (((lane & 7) | ((lane & 16) >> 1)) + nw * 64) * 272
                    + ((lane >> 3) & 1) * 16;
        #pragma unroll
        for (int kt = 0; kt < 8; ++kt) {
            uint32_t ah[4], al[4];
            ldsm_x4(ah[0], ah[1], ah[2], ah[3], wa + kt * 32);
            ldsm_x4(al[0], al[1], al[2], al[3], wa + (PWL - PWH) + kt * 32);
            #pragma unroll
            for (int nt = 0; nt < 4; ++nt) {
                uint32_t bh[4], bl[4];
                uint32_t base = xb + nt * (16 * 272) + kt * 32;
                ldsm_x4(bh[0], bh[1], bh[2], bh[3], base);
                ldsm_x4(bl[0], bl[1], bl[2], bl[3], base + (PXL - PXH));
                mma16816(acc[2 * nt],     ah, bh[0], bh[1]);
                mma16816(acc[2 * nt + 1], ah, bh[2], bh[3]);
                mma16816(acc[2 * nt],     al, bh[0], bh[1]);
                mma16816(acc[2 * nt + 1], al, bh[2], bh[3]);
                mma16816(acc[2 * nt],     ah, bl[0], bl[1]);
                mma16816(acc[2 * nt + 1], ah, bl[2], bl[3]);
            }
        }
    }

    if (m == 3) {                                  // skip -> d_out (fp32)
        #pragma unroll
        for (int g = 0; g < 8; ++g) {
            int n_g = nb * 128 + nw * 64 + g * 8 + (lane & 3) * 2;
            #pragma unroll
            for (int cc = 0; cc < 2; ++cc) {
                int o_g = h * 64 + mw * 16 + (lane >> 2) + cc * 8;
                float2 st = {acc[g][2 * cc], acc[g][2 * cc + 1]};
                *(float2*)(out + ((size_t)(b * OUTC + o_g)) * NTOT + n_g) = st;
            }
        }
    } else {                                       // q/k/v: stage [n][d] fp16 pitch 72h -> (p,n,d)
        float scale = (m == 0) ? 0.125f : 1.0f;
        __syncthreads();
        __half* S = (__half*)smem;
        #pragma unroll
        for (int g = 0; g < 8; ++g) {
            int n0 = nw * 64 + g * 8 + (lane & 3) * 2;
            #pragma unroll
            for (int cc = 0; cc < 2; ++cc) {
                int d = mw * 16 + (lane >> 2) + cc * 8;
                #pragma unroll
                for (int e = 0; e < 2; ++e)
                    S[(n0 + e) * 72 + d] = __float2half_rn(acc[g][2 * cc + e] * scale);
            }
        }
        __syncthreads();
        __half* dst = (m == 0 ? g_q : m == 1 ? g_k : g_v) + ((size_t)p * NTOT + nb * 128) * HD;
        #pragma unroll
        for (int l = 0; l < 4; ++l) {
            int idx = tid + l * 256;
            int n = idx >> 3, u = idx & 7;
            ((uint4*)dst)[idx] = *(const uint4*)((char*)S + n * 144 + u * 16);
        }
    }
}

// ============================================================
// K3: fused flash attention, single-term fp16 HMMA
//     Q fragments hoisted to registers; 128-row j-chunks,
//     two 64-row compute sub-passes. 2 CTAs/SM, grid (16 it, 16 p)
// ============================================================
#define PIT 144
#define AQ  0
#define AK0 18432
#define AV0 36864
#define AK1 55296
#define AV1 73728
#define SMEM_ATTN 92160

__device__ __forceinline__ void load_kv128(uint32_t sb, int p, int c, int s, int tid) {
    const char* gk = (const char*)(g_k + ((size_t)p * NTOT + c * 128) * HD);
    const char* gv = (const char*)(g_v + ((size_t)p * NTOT + c * 128) * HD);
    uint32_t kd = sb + (s ? AK1 : AK0);
    uint32_t vd = sb + (s ? AV1 : AV0);
    #pragma unroll
    for (int l = 0; l < 8; ++l) {
        int idx = tid + l * 128;                   // 1024 x 16B each
        int row = idx >> 3, c16 = (idx & 7) * 16;
        CP16(kd + row * PIT + c16, gk + row * 128 + c16);
        CP16(vd + row * PIT + c16, gv + row * 128 + c16);
    }
}

__global__ __launch_bounds__(128, 2) void attn_kernel(float* __restrict__ out)
{
    extern __shared__ __align__(1024) char smem[];
    uint32_t sb = smem_u32(smem);
    int tid = threadIdx.x, wid = tid >> 5, lane = tid & 31;
    int g = lane >> 2, t = lane & 3;
    int it = blockIdx.x, p = blockIdx.y;
    int b = p >> 2, h = p & 3;

    // ---- issue Q (128 rows x 128B) + chunk0 as group 0 ----
    {
        const char* gq = (const char*)(g_q + ((size_t)p * NTOT + it * 128) * HD);
        #pragma unroll
        for (int l = 0; l < 8; ++l) {
            int idx = tid + l * 128;
            int row = idx >> 3, c16 = (idx & 7) * 16;
            CP16(sb + AQ + row * PIT + c16, gq + row * 128 + c16);
        }
        load_kv128(sb, p, 0, 0, tid);
        CP_COMMIT();
    }

    uint32_t qa = sb + AQ + (wid * 32 + (lane & 15)) * PIT + (lane >> 4) * 16;
    uint32_t kb_rel = ((lane & 7) | ((lane & 16) >> 1)) * PIT + ((lane >> 3) & 1) * 16;
    uint32_t vb_rel = (lane & 15) * PIT + (lane >> 4) * 16;

    uint32_t qf[2][4][4];                          // Q fragments, chunk-invariant
    float o[2][8][4] = {};
    float rs[2][2] = {};

    for (int c = 0; c < NITER; ++c) {
        if (c) __syncthreads();
        if (c < NITER - 1) {
            load_kv128(sb, p, c + 1, (c + 1) & 1, tid);
            CP_COMMIT();
            CP_WAIT(1);
        } else {
            CP_WAIT(0);
        }
        __syncthreads();

        if (c == 0) {
            #pragma unroll
            for (int kt = 0; kt < 4; ++kt)
                #pragma unroll
                for (int mi = 0; mi < 2; ++mi)
                    ldsm_x4(qf[mi][kt][0], qf[mi][kt][1], qf[mi][kt][2], qf[mi][kt][3],
                            qa + mi * (16 * PIT) + kt * 32);
        }

        #pragma unroll
        for (int sub = 0; sub < 2; ++sub) {
            uint32_t kb = sb + ((c & 1) ? AK1 : AK0) + sub * (64 * PIT) + kb_rel;
            uint32_t vb = sb + ((c & 1) ? AV1 : AV0) + sub * (64 * PIT) + vb_rel;

            // ---- S = Q Kᵀ ----
            float s[2][8][4] = {};
            #pragma unroll
            for (int kt = 0; kt < 4; ++kt) {
                #pragma unroll
                for (int nt2 = 0; nt2 < 4; ++nt2) {
                    uint32_t bh[4];
                    ldsm_x4(bh[0], bh[1], bh[2], bh[3], kb + nt2 * (16 * PIT) + kt * 32);
                    #pragma unroll
                    for (int mi = 0; mi < 2; ++mi) {
                        mma16816h(s[mi][2 * nt2],     qf[mi][kt], bh[0], bh[1]);
                        mma16816h(s[mi][2 * nt2 + 1], qf[mi][kt], bh[2], bh[3]);
                    }
                }
            }

            // ---- per-kt: exp + fp16 pack, then P·V ----
            #pragma unroll
            for (int kt = 0; kt < 4; ++kt) {
                uint32_t ph[2][4];
                #pragma unroll
                for (int mi = 0; mi < 2; ++mi) {
                    #pragma unroll
                    for (int hf = 0; hf < 2; ++hf) {
                        float* sv = s[mi][2 * kt + hf];
                        float e0 = __expf(sv[0]), e1 = __expf(sv[1]);
                        float e2 = __expf(sv[2]), e3 = __expf(sv[3]);
                        rs[mi][0] += e0 + e1; rs[mi][1] += e2 + e3;
                        uint32_t h01, h23;
                        asm("cvt.rn.f16x2.f32 %0, %1, %2;" : "=r"(h01) : "f"(e1), "f"(e0));
                        asm("cvt.rn.f16x2.f32 %0, %1, %2;" : "=r"(h23) : "f"(e3), "f"(e2));
                        ph[mi][2 * hf] = h01; ph[mi][2 * hf + 1] = h23;
                    }
                }
                #pragma unroll
                for (int nt2 = 0; nt2 < 4; ++nt2) {
                    uint32_t bh[4];
                    ldsm_x4_t(bh[0], bh[1], bh[2], bh[3], vb + kt * (16 * PIT) + nt2 * 32);
                    #pragma unroll
                    for (int mi = 0; mi < 2; ++mi) {
                        mma16816h(o[mi][2 * nt2],     ph[mi], bh[0], bh[1]);
                        mma16816h(o[mi][2 * nt2 + 1], ph[mi], bh[2], bh[3]);
                    }
                }
            }
        }
    }

    // ---- rowsum reduce across quad, normalize, transpose via smem ----
    float inv[2][2];
    #pragma unroll
    for (int mi = 0; mi < 2; ++mi) {
        #pragma unroll
        for (int cc = 0; cc < 2; ++cc) {
            float v = rs[mi][cc];
            v += __shfl_xor_sync(0xffffffffu, v, 1);
            v += __shfl_xor_sync(0xffffffffu, v, 2);
            inv[mi][cc] = 1.0f / v;
        }
    }

    __syncthreads();
    float* Os = (float*)smem;                      // [64][129]
    #pragma unroll
    for (int mi = 0; mi < 2; ++mi) {
        int i0 = wid * 32 + mi * 16 + g;
        #pragma unroll
        for (int dt = 0; dt < 8; ++dt) {
            int d0 = dt * 8 + t * 2;
            Os[d0 * 129 + i0]           = o[mi][dt][0] * inv[mi][0];
            Os[(d0 + 1) * 129 + i0]     = o[mi][dt][1] * inv[mi][0];
            Os[d0 * 129 + i0 + 8]       = o[mi][dt][2] * inv[mi][1];
            Os[(d0 + 1) * 129 + i0 + 8] = o[mi][dt][3] * inv[mi][1];
        }
    }
    __syncthreads();

    #pragma unroll
    for (int l = 0; l < 64; ++l) {
        int idx = tid + l * 128;                   // 8192 elements
        int i = idx & 127, d = idx >> 7;
        size_t go = ((size_t)(b * OUTC + h * HD + d)) * NTOT + it * 128 + i;
        out[go] += Os[d * 129 + i];
    }
}

// ============================================================
extern "C" void kernel_launch(void* const* d_in, const int* in_sizes, int n_in,
                              void* d_out, int out_size)
{
    const float* pcd   = (const float*)d_in[0];
    const float* sel   = (const float*)d_in[1];
    const float* drp   = (const float*)d_in[2];
    const int*   isel  = (const int*)d_in[3];
    const int*   idrp  = (const int*)d_in[4];
    const float* Wq    = (const float*)d_in[5];
    const float* Wk    = (const float*)d_in[6];
    const float* Wv    = (const float*)d_in[7];
    const float* Wskip = (const float*)d_in[8];
    float* out = (float*)d_out;

    cudaFuncSetAttribute(proj_kernel, cudaFuncAttributeMaxDynamicSharedMemorySize, SMEM_PROJ);
    cudaFuncSetAttribute(attn_kernel, cudaFuncAttributeMaxDynamicSharedMemorySize, SMEM_ATTN);

    prep_kernel<<<dim3(64, 2, NB), 256>>>(sel, drp, isel, idrp, pcd);
    proj_kernel<<<dim3(16, 16, NB), 256, SMEM_PROJ>>>(Wq, Wk, Wv, Wskip, out);
    attn_kernel<<<dim3(16, NP), 128, SMEM_ATTN>>>(out);
}

// round 13
// speedup vs baseline: 1.0394x; 1.0394x over previous
#include <cuda_runtime.h>
#include <cuda_bf16.h>
#include <cuda_fp16.h>
#include <cstdint>

#define NB   4
#define CIN  128
#define NTOT 2048
#define NH   4
#define HD   64
#define OUTC 256
#define NP   16
#define NCHUNK 32

// ---------------- scratch ----------------
__device__ __half g_x[NB * NTOT * CIN];                // scattered input fp16 (b,n,c)
__device__ __nv_bfloat16 g_ph[NB * NTOT * CIN];        // pcd_up hi (b,n,c)
__device__ __nv_bfloat16 g_pl[NB * NTOT * CIN];        // pcd_up lo
__device__ __half g_q[NP * NTOT * HD];                 // (p,n,d) fp16, pre-scaled 1/8
__device__ __half g_k[NP * NTOT * HD];                 // (p,n,d) fp16
__device__ __half g_v[NP * NTOT * HD];                 // (p,n,d) fp16

// ---------------- helpers ----------------
__device__ __forceinline__ uint32_t smem_u32(const void* p) {
    uint32_t a;
    asm("{ .reg .u64 t; cvta.to.shared.u64 t, %1; cvt.u32.u64 %0, t; }" : "=r"(a) : "l"(p));
    return a;
}
__device__ __forceinline__ void ldsm_x4(uint32_t& r0, uint32_t& r1, uint32_t& r2, uint32_t& r3,
                                        uint32_t addr) {
    asm volatile("ldmatrix.sync.aligned.m8n8.x4.shared.b16 {%0,%1,%2,%3}, [%4];"
                 : "=r"(r0), "=r"(r1), "=r"(r2), "=r"(r3) : "r"(addr));
}
__device__ __forceinline__ void ldsm_x4_t(uint32_t& r0, uint32_t& r1, uint32_t& r2, uint32_t& r3,
                                          uint32_t addr) {
    asm volatile("ldmatrix.sync.aligned.m8n8.x4.trans.shared.b16 {%0,%1,%2,%3}, [%4];"
                 : "=r"(r0), "=r"(r1), "=r"(r2), "=r"(r3) : "r"(addr));
}
__device__ __forceinline__ void mma16816(float* d, const uint32_t* a, uint32_t b0, uint32_t b1) {
    asm volatile("mma.sync.aligned.m16n8k16.row.col.f32.bf16.bf16.f32 "
                 "{%0,%1,%2,%3}, {%4,%5,%6,%7}, {%8,%9}, {%0,%1,%2,%3};"
                 : "+f"(d[0]), "+f"(d[1]), "+f"(d[2]), "+f"(d[3])
                 : "r"(a[0]), "r"(a[1]), "r"(a[2]), "r"(a[3]), "r"(b0), "r"(b1));
}
__device__ __forceinline__ void mma16816h(float* d, const uint32_t* a, uint32_t b0, uint32_t b1) {
    asm volatile("mma.sync.aligned.m16n8k16.row.col.f32.f16.f16.f32 "
                 "{%0,%1,%2,%3}, {%4,%5,%6,%7}, {%8,%9}, {%0,%1,%2,%3};"
                 : "+f"(d[0]), "+f"(d[1]), "+f"(d[2]), "+f"(d[3])
                 : "r"(a[0]), "r"(a[1]), "r"(a[2]), "r"(a[3]), "r"(b0), "r"(b1));
}
#define CP16(dst, src) asm volatile("cp.async.cg.shared.global [%0], [%1], 16;" :: "r"(dst), "l"(src))
#define CP_COMMIT()    asm volatile("cp.async.commit_group;" ::: "memory")
#define CP_WAIT(n)     asm volatile("cp.async.wait_group %0;" :: "n"(n) : "memory")

__device__ __forceinline__ void split_bf16(float x, __nv_bfloat16& hi, __nv_bfloat16& lo) {
    hi = __float2bfloat16(x);
    lo = __float2bfloat16(x - __bfloat162float(hi));
}

// ============================================================
// K1: tiled transpose + scatter
// ============================================================
__global__ __launch_bounds__(256) void prep_kernel(
    const float* __restrict__ sel, const float* __restrict__ drp,
    const int* __restrict__ isel, const int* __restrict__ idrp,
    const float* __restrict__ pcd)
{
    __shared__ float S[128][33];
    __shared__ int dsts[32];
    int tx = blockIdx.x, mode = blockIdx.y, b = blockIdx.z;
    int t = threadIdx.x;

    if (mode == 0) {
        const float* src; const int* ip; int n0;
        if (tx < 32) { src = sel + (size_t)b * CIN * 1024; ip = isel; n0 = tx * 32; }
        else         { src = drp + (size_t)b * CIN * 1024; ip = idrp; n0 = tx * 32 - 1024; }
        #pragma unroll
        for (int i = 0; i < 16; ++i) {
            int idx = t + i * 256;
            int c = idx >> 5, n = idx & 31;
            S[c][n] = src[(size_t)c * 1024 + n0 + n];
        }
        if (t < 32) dsts[t] = ip[b * 1024 + n0 + t];
    } else {
        int n0 = tx * 32;
        #pragma unroll
        for (int i = 0; i < 16; ++i) {
            int idx = t + i * 256;
            int c = idx >> 5, n = idx & 31;
            S[c][n] = pcd[((size_t)b * CIN + c) * NTOT + n0 + n];
        }
        if (t < 32) dsts[t] = n0 + t;
    }
    __syncthreads();

    int n = t >> 3, cs = (t & 7) * 16;
    int dst = dsts[n];
    if (mode == 0) {
        __half* dx = g_x + ((size_t)(b * NTOT + dst)) * CIN + cs;
        __align__(16) __half hb[16];
        #pragma unroll
        for (int i = 0; i < 16; ++i) hb[i] = __float2half_rn(S[cs + i][n]);
        *(uint4*)dx       = *(uint4*)hb;
        *(uint4*)(dx + 8) = *(uint4*)(hb + 8);
    } else {
        __nv_bfloat16* dh = g_ph + ((size_t)(b * NTOT + dst)) * CIN + cs;
        __nv_bfloat16* dl = g_pl + ((size_t)(b * NTOT + dst)) * CIN + cs;
        __align__(16) __nv_bfloat16 hb[16], lb[16];
        #pragma unroll
        for (int i = 0; i < 16; ++i) split_bf16(S[cs + i][n], hb[i], lb[i]);
        *(uint4*)dh       = *(uint4*)hb;
        *(uint4*)(dh + 8) = *(uint4*)(hb + 8);
        *(uint4*)dl       = *(uint4*)lb;
        *(uint4*)(dl + 8) = *(uint4*)(lb + 8);
    }
}

// ============================================================
// K2: projections on tensor cores
//     m<3 (q/k/v): single-term fp16; m=3 (skip): 3-term bf16
// ============================================================
#define PW  0
#define PX  17408
#define PWH 0
#define PWL 17408
#define PXH 34816
#define PXL 69632
#define SMEM_PROJ 104448

__global__ __launch_bounds__(256, 2) void proj_kernel(
    const float* __restrict__ Wq, const float* __restrict__ Wk,
    const float* __restrict__ Wv, const float* __restrict__ Wskip,
    float* __restrict__ out)
{
    extern __shared__ __align__(1024) char smem[];
    uint32_t sb = smem_u32(smem);
    int tid = threadIdx.x, wid = tid >> 5, lane = tid & 31;
    int nb = blockIdx.x, ob = blockIdx.y, b = blockIdx.z;
    int m = ob >> 2, h = ob & 3;
    int p = b * NH + h;
    int mw = wid & 3, nw = wid >> 2;
    float acc[8][4] = {};

    if (m < 3) {
        const float* W = (m == 0 ? Wq : m == 1 ? Wk : Wv) + h * 64 * CIN;
        const __half* X = g_x + ((size_t)b * NTOT + nb * 128) * CIN;

        #pragma unroll
        for (int l = 0; l < 8; ++l) {
            int idx = tid + l * 256;
            int o = idx >> 5, c4 = (idx & 31) * 4;
            float4 w = *(const float4*)(W + o * 128 + c4);
            __align__(8) __half hw[4] = {
                __float2half_rn(w.x), __float2half_rn(w.y),
                __float2half_rn(w.z), __float2half_rn(w.w) };
            *(uint2*)(smem + PW + o * 272 + c4 * 2) = *(uint2*)hw;
        }
        #pragma unroll
        for (int l = 0; l < 8; ++l) {
            int idx = tid + l * 256;
            int n = idx >> 4, u = idx & 15;
            *(uint4*)(smem + PX + n * 272 + u * 16) = ((const uint4*)(X + (size_t)n * CIN))[u];
        }
        __syncthreads();

        uint32_t wa = sb + PW + (mw * 16 + (lane & 15)) * 272 + (lane >> 4) * 16;
        uint32_t xb = sb + PX + (((lane & 7) | ((lane & 16) >> 1)) + nw * 64) * 272
                    + ((lane >> 3) & 1) * 16;
        #pragma unroll
        for (int kt = 0; kt < 8; ++kt) {
            uint32_t ah[4];
            ldsm_x4(ah[0], ah[1], ah[2], ah[3], wa + kt * 32);
            #pragma unroll
            for (int nt = 0; nt < 4; ++nt) {
                uint32_t bh[4];
                ldsm_x4(bh[0], bh[1], bh[2], bh[3], xb + nt * (16 * 272) + kt * 32);
                mma16816h(acc[2 * nt],     ah, bh[0], bh[1]);
                mma16816h(acc[2 * nt + 1], ah, bh[2], bh[3]);
            }
        }
    } else {
        const float* W = Wskip + h * 64 * CIN;
        const __nv_bfloat16* Xh = g_ph + ((size_t)b * NTOT + nb * 128) * CIN;
        const __nv_bfloat16* Xl = g_pl + ((size_t)b * NTOT + nb * 128) * CIN;

        #pragma unroll
        for (int l = 0; l < 8; ++l) {
            int idx = tid + l * 256;
            int o = idx >> 5, c4 = (idx & 31) * 4;
            float4 w = *(const float4*)(W + o * 128 + c4);
            __nv_bfloat16 h0, h1, h2, h3, l0, l1, l2, l3;
            split_bf16(w.x, h0, l0); split_bf16(w.y, h1, l1);
            split_bf16(w.z, h2, l2); split_bf16(w.w, h3, l3);
            __nv_bfloat162* dh = (__nv_bfloat162*)(smem + PWH + o * 272 + c4 * 2);
            __nv_bfloat162* dl = (__nv_bfloat162*)(smem + PWL + o * 272 + c4 * 2);
            dh[0] = {h0, h1}; dh[1] = {h2, h3};
            dl[0] = {l0, l1}; dl[1] = {l2, l3};
        }
        #pragma unroll
        for (int l = 0; l < 8; ++l) {
            int idx = tid + l * 256;
            int n = idx >> 4, u = idx & 15;
            *(uint4*)(smem + PXH + n * 272 + u * 16) = ((const uint4*)(Xh + (size_t)n * CIN))[u];
            *(uint4*)(smem + PXL + n * 272 + u * 16) = ((const uint4*)(Xl + (size_t)n * CIN))[u];
        }
        __syncthreads();

        uint32_t wa = sb + PWH + (mw * 16 + (lane & 15)) * 272 + (lane >> 4) * 16;
        uint32_t xb = sb + PXH + (((lane & 7) | ((lane & 16) >> 1)) + nw * 64) * 272
                    + ((lane >> 3) & 1) * 16;
        #pragma unroll
        for (int kt = 0; kt < 8; ++kt) {
            uint32_t ah[4], al[4];
            ldsm_x4(ah[0], ah[1], ah[2], ah[3], wa + kt * 32);
            ldsm_x4(al[0], al[1], al[2], al[3], wa + (PWL - PWH) + kt * 32);
            #pragma unroll
            for (int nt = 0; nt < 4; ++nt) {
                uint32_t bh[4], bl[4];
                uint32_t base = xb + nt * (16 * 272) + kt * 32;
                ldsm_x4(bh[0], bh[1], bh[2], bh[3], base);
                ldsm_x4(bl[0], bl[1], bl[2], bl[3], base + (PXL - PXH));
                mma16816(acc[2 * nt],     ah, bh[0], bh[1]);
                mma16816(acc[2 * nt + 1], ah, bh[2], bh[3]);
                mma16816(acc[2 * nt],     al, bh[0], bh[1]);
                mma16816(acc[2 * nt + 1], al, bh[2], bh[3]);
                mma16816(acc[2 * nt],     ah, bl[0], bl[1]);
                mma16816(acc[2 * nt + 1], ah, bl[2], bl[3]);
            }
        }
    }

    if (m == 3) {                                  // skip -> d_out (fp32)
        #pragma unroll
        for (int g = 0; g < 8; ++g) {
            int n_g = nb * 128 + nw * 64 + g * 8 + (lane & 3) * 2;
            #pragma unroll
            for (int cc = 0; cc < 2; ++cc) {
                int o_g = h * 64 + mw * 16 + (lane >> 2) + cc * 8;
                float2 st = {acc[g][2 * cc], acc[g][2 * cc + 1]};
                *(float2*)(out + ((size_t)(b * OUTC + o_g)) * NTOT + n_g) = st;
            }
        }
    } else {                                       // q/k/v: stage [n][d] fp16 pitch 72h -> (p,n,d)
        float scale = (m == 0) ? 0.125f : 1.0f;
        __syncthreads();
        __half* S = (__half*)smem;
        #pragma unroll
        for (int g = 0; g < 8; ++g) {
            int n0 = nw * 64 + g * 8 + (lane & 3) * 2;
            #pragma unroll
            for (int cc = 0; cc < 2; ++cc) {
                int d = mw * 16 + (lane >> 2) + cc * 8;
                #pragma unroll
                for (int e = 0; e < 2; ++e)
                    S[(n0 + e) * 72 + d] = __float2half_rn(acc[g][2 * cc + e] * scale);
            }
        }
        __syncthreads();
        __half* dst = (m == 0 ? g_q : m == 1 ? g_k : g_v) + ((size_t)p * NTOT + nb * 128) * HD;
        #pragma unroll
        for (int l = 0; l < 4; ++l) {
            int idx = tid + l * 256;
            int n = idx >> 3, u = idx & 7;
            ((uint4*)dst)[idx] = *(const uint4*)((char*)S + n * 144 + u * 16);
        }
    }
}

// ============================================================
// K3: fused flash attention, single-term fp16 HMMA
//     R11 structure (64-row chunks) + Q fragments hoisted to regs
//     4 warps x M=32 = 128 rows/CTA, 2 CTAs/SM, grid (16 it, 16 p)
// ============================================================
#define PIT 144
#define AQ  0
#define AK0 18432
#define AK1 27648
#define AV0 36864
#define AV1 46080
#define SMEM_ATTN 55296

__device__ __forceinline__ void load_kv(uint32_t sb, int p, int c, int s, int tid) {
    const char* gk = (const char*)(g_k + ((size_t)p * NTOT + c * 64) * HD);
    const char* gv = (const char*)(g_v + ((size_t)p * NTOT + c * 64) * HD);
    uint32_t kd = sb + (s ? AK1 : AK0);
    uint32_t vd = sb + (s ? AV1 : AV0);
    #pragma unroll
    for (int l = 0; l < 4; ++l) {
        int idx = tid + l * 128;                   // 512 x 16B each
        int row = idx >> 3, c16 = (idx & 7) * 16;
        CP16(kd + row * PIT + c16, gk + row * 128 + c16);
        CP16(vd + row * PIT + c16, gv + row * 128 + c16);
    }
}

__global__ __launch_bounds__(128, 2) void attn_kernel(float* __restrict__ out)
{
    extern __shared__ __align__(1024) char smem[];
    uint32_t sb = smem_u32(smem);
    int tid = threadIdx.x, wid = tid >> 5, lane = tid & 31;
    int g = lane >> 2, t = lane & 3;
    int it = blockIdx.x, p = blockIdx.y;
    int b = p >> 2, h = p & 3;

    // ---- issue Q (128 rows x 128B) + chunk0 as group 0 ----
    {
        const char* gq = (const char*)(g_q + ((size_t)p * NTOT + it * 128) * HD);
        #pragma unroll
        for (int l = 0; l < 8; ++l) {
            int idx = tid + l * 128;               // 1024 x 16B
            int row = idx >> 3, c16 = (idx & 7) * 16;
            CP16(sb + AQ + row * PIT + c16, gq + row * 128 + c16);
        }
        load_kv(sb, p, 0, 0, tid);
        CP_COMMIT();
    }

    uint32_t qa = sb + AQ + (wid * 32 + (lane & 15)) * PIT + (lane >> 4) * 16;
    uint32_t kb_rel = ((lane & 7) | ((lane & 16) >> 1)) * PIT + ((lane >> 3) & 1) * 16;
    uint32_t vb_rel = (lane & 15) * PIT + (lane >> 4) * 16;

    uint32_t qf[2][4][4];                          // Q fragments, chunk-invariant
    float o[2][8][4] = {};
    float rs[2][2] = {};

    for (int c = 0; c < NCHUNK; ++c) {
        if (c) __syncthreads();
        if (c < NCHUNK - 1) {
            load_kv(sb, p, c + 1, (c + 1) & 1, tid);
            CP_COMMIT();
            CP_WAIT(1);
        } else {
            CP_WAIT(0);
        }
        __syncthreads();

        if (c == 0) {                              // hoist Q fragments once
            #pragma unroll
            for (int kt = 0; kt < 4; ++kt)
                #pragma unroll
                for (int mi = 0; mi < 2; ++mi)
                    ldsm_x4(qf[mi][kt][0], qf[mi][kt][1], qf[mi][kt][2], qf[mi][kt][3],
                            qa + mi * (16 * PIT) + kt * 32);
        }

        uint32_t kb = sb + ((c & 1) ? AK1 : AK0) + kb_rel;
        uint32_t vb = sb + ((c & 1) ? AV1 : AV0) + vb_rel;

        // ---- S = Q Kᵀ (single-term fp16) ----
        float s[2][8][4] = {};
        #pragma unroll
        for (int kt = 0; kt < 4; ++kt) {
            #pragma unroll
            for (int nt2 = 0; nt2 < 4; ++nt2) {
                uint32_t bh[4];
                ldsm_x4(bh[0], bh[1], bh[2], bh[3], kb + nt2 * (16 * PIT) + kt * 32);
                #pragma unroll
                for (int mi = 0; mi < 2; ++mi) {
                    mma16816h(s[mi][2 * nt2],     qf[mi][kt], bh[0], bh[1]);
                    mma16816h(s[mi][2 * nt2 + 1], qf[mi][kt], bh[2], bh[3]);
                }
            }
        }

        // ---- per-kt: exp + fp16 pack, then P·V (V via trans-ldmatrix) ----
        #pragma unroll
        for (int kt = 0; kt < 4; ++kt) {
            uint32_t ph[2][4];
            #pragma unroll
            for (int mi = 0; mi < 2; ++mi) {
                #pragma unroll
                for (int hf = 0; hf < 2; ++hf) {
                    float* sv = s[mi][2 * kt + hf];
                    float e0 = __expf(sv[0]), e1 = __expf(sv[1]);
                    float e2 = __expf(sv[2]), e3 = __expf(sv[3]);
                    rs[mi][0] += e0 + e1; rs[mi][1] += e2 + e3;
                    uint32_t h01, h23;
                    asm("cvt.rn.f16x2.f32 %0, %1, %2;" : "=r"(h01) : "f"(e1), "f"(e0));
                    asm("cvt.rn.f16x2.f32 %0, %1, %2;" : "=r"(h23) : "f"(e3), "f"(e2));
                    ph[mi][2 * hf] = h01; ph[mi][2 * hf + 1] = h23;
                }
            }
            #pragma unroll
            for (int nt2 = 0; nt2 < 4; ++nt2) {
                uint32_t bh[4];
                ldsm_x4_t(bh[0], bh[1], bh[2], bh[3], vb + kt * (16 * PIT) + nt2 * 32);
                #pragma unroll
                for (int mi = 0; mi < 2; ++mi) {
                    mma16816h(o[mi][2 * nt2],     ph[mi], bh[0], bh[1]);
                    mma16816h(o[mi][2 * nt2 + 1], ph[mi], bh[2], bh[3]);
                }
            }
        }
    }

    // ---- rowsum reduce across quad, normalize, transpose via smem ----
    float inv[2][2];
    #pragma unroll
    for (int mi = 0; mi < 2; ++mi) {
        #pragma unroll
        for (int cc = 0; cc < 2; ++cc) {
            float v = rs[mi][cc];
            v += __shfl_xor_sync(0xffffffffu, v, 1);
            v += __shfl_xor_sync(0xffffffffu, v, 2);
            inv[mi][cc] = 1.0f / v;
        }
    }

    __syncthreads();
    float* Os = (float*)smem;                      // [64][129]
    #pragma unroll
    for (int mi = 0; mi < 2; ++mi) {
        int i0 = wid * 32 + mi * 16 + g;
        #pragma unroll
        for (int dt = 0; dt < 8; ++dt) {
            int d0 = dt * 8 + t * 2;
            Os[d0 * 129 + i0]           = o[mi][dt][0] * inv[mi][0];
            Os[(d0 + 1) * 129 + i0]     = o[mi][dt][1] * inv[mi][0];
            Os[d0 * 129 + i0 + 8]       = o[mi][dt][2] * inv[mi][1];
            Os[(d0 + 1) * 129 + i0 + 8] = o[mi][dt][3] * inv[mi][1];
        }
    }
    __syncthreads();

    #pragma unroll
    for (int l = 0; l < 64; ++l) {
        int idx = tid + l * 128;                   // 8192 elements
        int i = idx & 127, d = idx >> 7;
        size_t go = ((size_t)(b * OUTC + h * HD + d)) * NTOT + it * 128 + i;
        out[go] += Os[d * 129 + i];
    }
}

// ============================================================
extern "C" void kernel_launch(void* const* d_in, const int* in_sizes, int n_in,
                              void* d_out, int out_size)
{
    const float* pcd   = (const float*)d_in[0];
    const float* sel   = (const float*)d_in[1];
    const float* drp   = (const float*)d_in[2];
    const int*   isel  = (const int*)d_in[3];
    const int*   idrp  = (const int*)d_in[4];
    const float* Wq    = (const float*)d_in[5];
    const float* Wk    = (const float*)d_in[6];
    const float* Wv    = (const float*)d_in[7];
    const float* Wskip = (const float*)d_in[8];
    float* out = (float*)d_out;

    cudaFuncSetAttribute(proj_kernel, cudaFuncAttributeMaxDynamicSharedMemorySize, SMEM_PROJ);
    cudaFuncSetAttribute(attn_kernel, cudaFuncAttributeMaxDynamicSharedMemorySize, SMEM_ATTN);

    prep_kernel<<<dim3(64, 2, NB), 256>>>(sel, drp, isel, idrp, pcd);
    proj_kernel<<<dim3(16, 16, NB), 256, SMEM_PROJ>>>(Wq, Wk, Wv, Wskip, out);
    attn_kernel<<<dim3(16, NP), 128, SMEM_ATTN>>>(out);
}

// round 14
// speedup vs baseline: 1.0688x; 1.0282x over previous
#include <cuda_runtime.h>
#include <cuda_bf16.h>
#include <cuda_fp16.h>
#include <cstdint>

#define NB   4
#define CIN  128
#define NTOT 2048
#define NH   4
#define HD   64
#define OUTC 256
#define NP   16
#define NCHUNK 32

// ---------------- scratch ----------------
__device__ __half g_x[NB * NTOT * CIN];                // scattered input fp16 (b,n,c)
__device__ __nv_bfloat16 g_ph[NB * NTOT * CIN];        // pcd_up hi (b,n,c)
__device__ __nv_bfloat16 g_pl[NB * NTOT * CIN];        // pcd_up lo
__device__ __half g_q[NP * NTOT * HD];                 // (p,n,d) fp16, pre-scaled 1/8
__device__ __half g_k[NP * NTOT * HD];                 // (p,n,d) fp16
__device__ __half g_v[NP * NTOT * HD];                 // (p,n,d) fp16

// ---------------- helpers ----------------
__device__ __forceinline__ uint32_t smem_u32(const void* p) {
    uint32_t a;
    asm("{ .reg .u64 t; cvta.to.shared.u64 t, %1; cvt.u32.u64 %0, t; }" : "=r"(a) : "l"(p));
    return a;
}
__device__ __forceinline__ void ldsm_x4(uint32_t& r0, uint32_t& r1, uint32_t& r2, uint32_t& r3,
                                        uint32_t addr) {
    asm volatile("ldmatrix.sync.aligned.m8n8.x4.shared.b16 {%0,%1,%2,%3}, [%4];"
                 : "=r"(r0), "=r"(r1), "=r"(r2), "=r"(r3) : "r"(addr));
}
__device__ __forceinline__ void ldsm_x4_t(uint32_t& r0, uint32_t& r1, uint32_t& r2, uint32_t& r3,
                                          uint32_t addr) {
    asm volatile("ldmatrix.sync.aligned.m8n8.x4.trans.shared.b16 {%0,%1,%2,%3}, [%4];"
                 : "=r"(r0), "=r"(r1), "=r"(r2), "=r"(r3) : "r"(addr));
}
__device__ __forceinline__ void mma16816(float* d, const uint32_t* a, uint32_t b0, uint32_t b1) {
    asm volatile("mma.sync.aligned.m16n8k16.row.col.f32.bf16.bf16.f32 "
                 "{%0,%1,%2,%3}, {%4,%5,%6,%7}, {%8,%9}, {%0,%1,%2,%3};"
                 : "+f"(d[0]), "+f"(d[1]), "+f"(d[2]), "+f"(d[3])
                 : "r"(a[0]), "r"(a[1]), "r"(a[2]), "r"(a[3]), "r"(b0), "r"(b1));
}
__device__ __forceinline__ void mma16816h(float* d, const uint32_t* a, uint32_t b0, uint32_t b1) {
    asm volatile("mma.sync.aligned.m16n8k16.row.col.f32.f16.f16.f32 "
                 "{%0,%1,%2,%3}, {%4,%5,%6,%7}, {%8,%9}, {%0,%1,%2,%3};"
                 : "+f"(d[0]), "+f"(d[1]), "+f"(d[2]), "+f"(d[3])
                 : "r"(a[0]), "r"(a[1]), "r"(a[2]), "r"(a[3]), "r"(b0), "r"(b1));
}
#define CP16(dst, src) asm volatile("cp.async.cg.shared.global [%0], [%1], 16;" :: "r"(dst), "l"(src))
#define CP_COMMIT()    asm volatile("cp.async.commit_group;" ::: "memory")
#define CP_WAIT(n)     asm volatile("cp.async.wait_group %0;" :: "n"(n) : "memory")

__device__ __forceinline__ void split_bf16(float x, __nv_bfloat16& hi, __nv_bfloat16& lo) {
    hi = __float2bfloat16(x);
    lo = __float2bfloat16(x - __bfloat162float(hi));
}

// ============================================================
// K1: tiled transpose + scatter
// ============================================================
__global__ __launch_bounds__(256) void prep_kernel(
    const float* __restrict__ sel, const float* __restrict__ drp,
    const int* __restrict__ isel, const int* __restrict__ idrp,
    const float* __restrict__ pcd)
{
    __shared__ float S[128][33];
    __shared__ int dsts[32];
    int tx = blockIdx.x, mode = blockIdx.y, b = blockIdx.z;
    int t = threadIdx.x;

    if (mode == 0) {
        const float* src; const int* ip; int n0;
        if (tx < 32) { src = sel + (size_t)b * CIN * 1024; ip = isel; n0 = tx * 32; }
        else         { src = drp + (size_t)b * CIN * 1024; ip = idrp; n0 = tx * 32 - 1024; }
        #pragma unroll
        for (int i = 0; i < 16; ++i) {
            int idx = t + i * 256;
            int c = idx >> 5, n = idx & 31;
            S[c][n] = src[(size_t)c * 1024 + n0 + n];
        }
        if (t < 32) dsts[t] = ip[b * 1024 + n0 + t];
    } else {
        int n0 = tx * 32;
        #pragma unroll
        for (int i = 0; i < 16; ++i) {
            int idx = t + i * 256;
            int c = idx >> 5, n = idx & 31;
            S[c][n] = pcd[((size_t)b * CIN + c) * NTOT + n0 + n];
        }
        if (t < 32) dsts[t] = n0 + t;
    }
    __syncthreads();

    int n = t >> 3, cs = (t & 7) * 16;
    int dst = dsts[n];
    if (mode == 0) {
        __half* dx = g_x + ((size_t)(b * NTOT + dst)) * CIN + cs;
        __align__(16) __half hb[16];
        #pragma unroll
        for (int i = 0; i < 16; ++i) hb[i] = __float2half_rn(S[cs + i][n]);
        *(uint4*)dx       = *(uint4*)hb;
        *(uint4*)(dx + 8) = *(uint4*)(hb + 8);
    } else {
        __nv_bfloat16* dh = g_ph + ((size_t)(b * NTOT + dst)) * CIN + cs;
        __nv_bfloat16* dl = g_pl + ((size_t)(b * NTOT + dst)) * CIN + cs;
        __align__(16) __nv_bfloat16 hb[16], lb[16];
        #pragma unroll
        for (int i = 0; i < 16; ++i) split_bf16(S[cs + i][n], hb[i], lb[i]);
        *(uint4*)dh       = *(uint4*)hb;
        *(uint4*)(dh + 8) = *(uint4*)(hb + 8);
        *(uint4*)dl       = *(uint4*)lb;
        *(uint4*)(dl + 8) = *(uint4*)(lb + 8);
    }
}

// ============================================================
// K2: projections on tensor cores
//     ob<4: q+k+v fused for head ob (fp16, X loaded once)
//     ob>=4: skip head ob-4 (3-term bf16)
// ============================================================
#define PQW 0            // 3 x 17408 W tiles (q,k,v)
#define PQX 52224        // X fp16 tile
#define PQS 87040        // staging 18432
#define PWH 0
#define PWL 17408
#define PXH 34816
#define PXL 69632
#define SMEM_PROJ 105472

__global__ __launch_bounds__(256, 2) void proj_kernel(
    const float* __restrict__ Wq, const float* __restrict__ Wk,
    const float* __restrict__ Wv, const float* __restrict__ Wskip,
    float* __restrict__ out)
{
    extern __shared__ __align__(1024) char smem[];
    uint32_t sb = smem_u32(smem);
    int tid = threadIdx.x, wid = tid >> 5, lane = tid & 31;
    int nb = blockIdx.x, ob = blockIdx.y, b = blockIdx.z;
    int mw = wid & 3, nw = wid >> 2;

    if (ob < 4) {
        // ================= fused q/k/v for head h =================
        int h = ob;
        int p = b * NH + h;
        const float* Wm[3] = { Wq + h * 64 * CIN, Wk + h * 64 * CIN, Wv + h * 64 * CIN };
        const __half* X = g_x + ((size_t)b * NTOT + nb * 128) * CIN;

        // ---- W x3 fp32 -> smem fp16 (64 x 128 each, pitch 272) ----
        #pragma unroll
        for (int l = 0; l < 24; ++l) {
            int idx = tid + l * 256;               // 6144 float4
            int mm = idx >> 11;
            int i2 = idx & 2047;
            int o = i2 >> 5, c4 = (i2 & 31) * 4;
            float4 w = *(const float4*)(Wm[mm] + o * 128 + c4);
            __align__(8) __half hw[4] = {
                __float2half_rn(w.x), __float2half_rn(w.y),
                __float2half_rn(w.z), __float2half_rn(w.w) };
            *(uint2*)(smem + PQW + mm * 17408 + o * 272 + c4 * 2) = *(uint2*)hw;
        }
        // ---- X: 128 n-rows x 256B, pitch 272 ----
        #pragma unroll
        for (int l = 0; l < 8; ++l) {
            int idx = tid + l * 256;               // 2048 uint4
            int n = idx >> 4, u = idx & 15;
            *(uint4*)(smem + PQX + n * 272 + u * 16) = ((const uint4*)(X + (size_t)n * CIN))[u];
        }
        __syncthreads();

        uint32_t wa_rel = (mw * 16 + (lane & 15)) * 272 + (lane >> 4) * 16;
        uint32_t xb = sb + PQX + (((lane & 7) | ((lane & 16) >> 1)) + nw * 64) * 272
                    + ((lane >> 3) & 1) * 16;
        float acc[3][8][4] = {};

        #pragma unroll
        for (int kt = 0; kt < 8; ++kt) {
            uint32_t ah[3][4];
            #pragma unroll
            for (int mm = 0; mm < 3; ++mm)
                ldsm_x4(ah[mm][0], ah[mm][1], ah[mm][2], ah[mm][3],
                        sb + PQW + mm * 17408 + wa_rel + kt * 32);
            #pragma unroll
            for (int nt = 0; nt < 4; ++nt) {
                uint32_t bh[4];
                ldsm_x4(bh[0], bh[1], bh[2], bh[3], xb + nt * (16 * 272) + kt * 32);
                #pragma unroll
                for (int mm = 0; mm < 3; ++mm) {
                    mma16816h(acc[mm][2 * nt],     ah[mm], bh[0], bh[1]);
                    mma16816h(acc[mm][2 * nt + 1], ah[mm], bh[2], bh[3]);
                }
            }
        }

        // ---- epilogues: stage [n][d] fp16 (pitch 144B), copy to (p,n,d) ----
        __half* S = (__half*)(smem + PQS);
        #pragma unroll
        for (int mm = 0; mm < 3; ++mm) {
            float scale = (mm == 0) ? 0.125f : 1.0f;
            __syncthreads();                       // staging free (prev copy done / X reads done)
            #pragma unroll
            for (int g = 0; g < 8; ++g) {
                int n0 = nw * 64 + g * 8 + (lane & 3) * 2;
                #pragma unroll
                for (int cc = 0; cc < 2; ++cc) {
                    int d = mw * 16 + (lane >> 2) + cc * 8;
                    #pragma unroll
                    for (int e = 0; e < 2; ++e)
                        S[(n0 + e) * 72 + d] = __float2half_rn(acc[mm][g][2 * cc + e] * scale);
                }
            }
            __syncthreads();
            __half* dst = (mm == 0 ? g_q : mm == 1 ? g_k : g_v)
                        + ((size_t)p * NTOT + nb * 128) * HD;
            #pragma unroll
            for (int l = 0; l < 4; ++l) {
                int idx = tid + l * 256;           // 1024 uint4
                int n = idx >> 3, u = idx & 7;
                ((uint4*)dst)[idx] = *(const uint4*)((char*)S + n * 144 + u * 16);
            }
        }
    } else {
        // ================= skip head (3-term bf16) =================
        int h = ob - 4;
        const float* W = Wskip + h * 64 * CIN;
        const __nv_bfloat16* Xh = g_ph + ((size_t)b * NTOT + nb * 128) * CIN;
        const __nv_bfloat16* Xl = g_pl + ((size_t)b * NTOT + nb * 128) * CIN;

        #pragma unroll
        for (int l = 0; l < 8; ++l) {
            int idx = tid + l * 256;               // 2048 float4
            int o = idx >> 5, c4 = (idx & 31) * 4;
            float4 w = *(const float4*)(W + o * 128 + c4);
            __nv_bfloat16 h0, h1, h2, h3, l0, l1, l2, l3;
            split_bf16(w.x, h0, l0); split_bf16(w.y, h1, l1);
            split_bf16(w.z, h2, l2); split_bf16(w.w, h3, l3);
            __nv_bfloat162* dh = (__nv_bfloat162*)(smem + PWH + o * 272 + c4 * 2);
            __nv_bfloat162* dl = (__nv_bfloat162*)(smem + PWL + o * 272 + c4 * 2);
            dh[0] = {h0, h1}; dh[1] = {h2, h3};
            dl[0] = {l0, l1}; dl[1] = {l2, l3};
        }
        #pragma unroll
        for (int l = 0; l < 8; ++l) {
            int idx = tid + l * 256;               // 2048 uint4
            int n = idx >> 4, u = idx & 15;
            *(uint4*)(smem + PXH + n * 272 + u * 16) = ((const uint4*)(Xh + (size_t)n * CIN))[u];
            *(uint4*)(smem + PXL + n * 272 + u * 16) = ((const uint4*)(Xl + (size_t)n * CIN))[u];
        }
        __syncthreads();

        uint32_t wa = sb + PWH + (mw * 16 + (lane & 15)) * 272 + (lane >> 4) * 16;
        uint32_t xb = sb + PXH + (((lane & 7) | ((lane & 16) >> 1)) + nw * 64) * 272
                    + ((lane >> 3) & 1) * 16;
        float acc[8][4] = {};

        #pragma unroll
        for (int kt = 0; kt < 8; ++kt) {
            uint32_t ah[4], al[4];
            ldsm_x4(ah[0], ah[1], ah[2], ah[3], wa + kt * 32);
            ldsm_x4(al[0], al[1], al[2], al[3], wa + (PWL - PWH) + kt * 32);
            #pragma unroll
            for (int nt = 0; nt < 4; ++nt) {
                uint32_t bh[4], bl[4];
                uint32_t base = xb + nt * (16 * 272) + kt * 32;
                ldsm_x4(bh[0], bh[1], bh[2], bh[3], base);
                ldsm_x4(bl[0], bl[1], bl[2], bl[3], base + (PXL - PXH));
                mma16816(acc[2 * nt],     ah, bh[0], bh[1]);
                mma16816(acc[2 * nt + 1], ah, bh[2], bh[3]);
                mma16816(acc[2 * nt],     al, bh[0], bh[1]);
                mma16816(acc[2 * nt + 1], al, bh[2], bh[3]);
                mma16816(acc[2 * nt],     ah, bl[0], bl[1]);
                mma16816(acc[2 * nt + 1], ah, bl[2], bl[3]);
            }
        }

        #pragma unroll
        for (int g = 0; g < 8; ++g) {
            int n_g = nb * 128 + nw * 64 + g * 8 + (lane & 3) * 2;
            #pragma unroll
            for (int cc = 0; cc < 2; ++cc) {
                int o_g = h * 64 + mw * 16 + (lane >> 2) + cc * 8;
                float2 st = {acc[g][2 * cc], acc[g][2 * cc + 1]};
                *(float2*)(out + ((size_t)(b * OUTC + o_g)) * NTOT + n_g) = st;
            }
        }
    }
}

// ============================================================
// K3: fused flash attention, single-term fp16 HMMA (R11 exact)
//     4 warps x M=32 = 128 rows/CTA, 2 CTAs/SM, grid (16 it, 16 p)
// ============================================================
#define PIT 144
#define AQ  0
#define AK0 18432
#define AK1 27648
#define AV0 36864
#define AV1 46080
#define SMEM_ATTN 55296

__device__ __forceinline__ void load_kv(uint32_t sb, int p, int c, int s, int tid) {
    const char* gk = (const char*)(g_k + ((size_t)p * NTOT + c * 64) * HD);
    const char* gv = (const char*)(g_v + ((size_t)p * NTOT + c * 64) * HD);
    uint32_t kd = sb + (s ? AK1 : AK0);
    uint32_t vd = sb + (s ? AV1 : AV0);
    #pragma unroll
    for (int l = 0; l < 4; ++l) {
        int idx = tid + l * 128;                   // 512 x 16B each
        int row = idx >> 3, c16 = (idx & 7) * 16;
        CP16(kd + row * PIT + c16, gk + row * 128 + c16);
        CP16(vd + row * PIT + c16, gv + row * 128 + c16);
    }
}

__global__ __launch_bounds__(128, 2) void attn_kernel(float* __restrict__ out)
{
    extern __shared__ __align__(1024) char smem[];
    uint32_t sb = smem_u32(smem);
    int tid = threadIdx.x, wid = tid >> 5, lane = tid & 31;
    int g = lane >> 2, t = lane & 3;
    int it = blockIdx.x, p = blockIdx.y;
    int b = p >> 2, h = p & 3;

    // ---- issue Q (128 rows x 128B) + chunk0 as group 0 ----
    {
        const char* gq = (const char*)(g_q + ((size_t)p * NTOT + it * 128) * HD);
        #pragma unroll
        for (int l = 0; l < 8; ++l) {
            int idx = tid + l * 128;               // 1024 x 16B
            int row = idx >> 3, c16 = (idx & 7) * 16;
            CP16(sb + AQ + row * PIT + c16, gq + row * 128 + c16);
        }
        load_kv(sb, p, 0, 0, tid);
        CP_COMMIT();
    }

    uint32_t qa = sb + AQ + (wid * 32 + (lane & 15)) * PIT + (lane >> 4) * 16;
    uint32_t kb_rel = ((lane & 7) | ((lane & 16) >> 1)) * PIT + ((lane >> 3) & 1) * 16;
    uint32_t vb_rel = (lane & 15) * PIT + (lane >> 4) * 16;

    float o[2][8][4] = {};
    float rs[2][2] = {};

    for (int c = 0; c < NCHUNK; ++c) {
        if (c) __syncthreads();
        if (c < NCHUNK - 1) {
            load_kv(sb, p, c + 1, (c + 1) & 1, tid);
            CP_COMMIT();
            CP_WAIT(1);
        } else {
            CP_WAIT(0);
        }
        __syncthreads();

        uint32_t kb = sb + ((c & 1) ? AK1 : AK0) + kb_rel;
        uint32_t vb = sb + ((c & 1) ? AV1 : AV0) + vb_rel;

        // ---- S = Q Kᵀ (single-term fp16) ----
        float s[2][8][4] = {};
        #pragma unroll
        for (int kt = 0; kt < 4; ++kt) {
            uint32_t aq[2][4];
            #pragma unroll
            for (int mi = 0; mi < 2; ++mi)
                ldsm_x4(aq[mi][0], aq[mi][1], aq[mi][2], aq[mi][3],
                        qa + mi * (16 * PIT) + kt * 32);
            #pragma unroll
            for (int nt2 = 0; nt2 < 4; ++nt2) {
                uint32_t bh[4];
                ldsm_x4(bh[0], bh[1], bh[2], bh[3], kb + nt2 * (16 * PIT) + kt * 32);
                #pragma unroll
                for (int mi = 0; mi < 2; ++mi) {
                    mma16816h(s[mi][2 * nt2],     aq[mi], bh[0], bh[1]);
                    mma16816h(s[mi][2 * nt2 + 1], aq[mi], bh[2], bh[3]);
                }
            }
        }

        // ---- per-kt: exp + fp16 pack, then P·V (V via trans-ldmatrix) ----
        #pragma unroll
        for (int kt = 0; kt < 4; ++kt) {
            uint32_t ph[2][4];
            #pragma unroll
            for (int mi = 0; mi < 2; ++mi) {
                #pragma unroll
                for (int hf = 0; hf < 2; ++hf) {
                    float* sv = s[mi][2 * kt + hf];
                    float e0 = __expf(sv[0]), e1 = __expf(sv[1]);
                    float e2 = __expf(sv[2]), e3 = __expf(sv[3]);
                    rs[mi][0] += e0 + e1; rs[mi][1] += e2 + e3;
                    uint32_t h01, h23;
                    asm("cvt.rn.f16x2.f32 %0, %1, %2;" : "=r"(h01) : "f"(e1), "f"(e0));
                    asm("cvt.rn.f16x2.f32 %0, %1, %2;" : "=r"(h23) : "f"(e3), "f"(e2));
                    ph[mi][2 * hf] = h01; ph[mi][2 * hf + 1] = h23;
                }
            }
            #pragma unroll
            for (int nt2 = 0; nt2 < 4; ++nt2) {
                uint32_t bh[4];
                ldsm_x4_t(bh[0], bh[1], bh[2], bh[3], vb + kt * (16 * PIT) + nt2 * 32);
                #pragma unroll
                for (int mi = 0; mi < 2; ++mi) {
                    mma16816h(o[mi][2 * nt2],     ph[mi], bh[0], bh[1]);
                    mma16816h(o[mi][2 * nt2 + 1], ph[mi], bh[2], bh[3]);
                }
            }
        }
    }

    // ---- rowsum reduce across quad, normalize, transpose via smem ----
    float inv[2][2];
    #pragma unroll
    for (int mi = 0; mi < 2; ++mi) {
        #pragma unroll
        for (int cc = 0; cc < 2; ++cc) {
            float v = rs[mi][cc];
            v += __shfl_xor_sync(0xffffffffu, v, 1);
            v += __shfl_xor_sync(0xffffffffu, v, 2);
            inv[mi][cc] = 1.0f / v;
        }
    }

    __syncthreads();
    float* Os = (float*)smem;                      // [64][129]
    #pragma unroll
    for (int mi = 0; mi < 2; ++mi) {
        int i0 = wid * 32 + mi * 16 + g;
        #pragma unroll
        for (int dt = 0; dt < 8; ++dt) {
            int d0 = dt * 8 + t * 2;
            Os[d0 * 129 + i0]           = o[mi][dt][0] * inv[mi][0];
            Os[(d0 + 1) * 129 + i0]     = o[mi][dt][1] * inv[mi][0];
            Os[d0 * 129 + i0 + 8]       = o[mi][dt][2] * inv[mi][1];
            Os[(d0 + 1) * 129 + i0 + 8] = o[mi][dt][3] * inv[mi][1];
        }
    }
    __syncthreads();

    #pragma unroll
    for (int l = 0; l < 64; ++l) {
        int idx = tid + l * 128;                   // 8192 elements
        int i = idx & 127, d = idx >> 7;
        size_t go = ((size_t)(b * OUTC + h * HD + d)) * NTOT + it * 128 + i;
        out[go] += Os[d * 129 + i];
    }
}

// ============================================================
extern "C" void kernel_launch(void* const* d_in, const int* in_sizes, int n_in,
                              void* d_out, int out_size)
{
    const float* pcd   = (const float*)d_in[0];
    const float* sel   = (const float*)d_in[1];
    const float* drp   = (const float*)d_in[2];
    const int*   isel  = (const int*)d_in[3];
    const int*   idrp  = (const int*)d_in[4];
    const float* Wq    = (const float*)d_in[5];
    const float* Wk    = (const float*)d_in[6];
    const float* Wv    = (const float*)d_in[7];
    const float* Wskip = (const float*)d_in[8];
    float* out = (float*)d_out;

    cudaFuncSetAttribute(proj_kernel, cudaFuncAttributeMaxDynamicSharedMemorySize, SMEM_PROJ);
    cudaFuncSetAttribute(attn_kernel, cudaFuncAttributeMaxDynamicSharedMemorySize, SMEM_ATTN);

    prep_kernel<<<dim3(64, 2, NB), 256>>>(sel, drp, isel, idrp, pcd);
    proj_kernel<<<dim3(16, 8, NB), 256, SMEM_PROJ>>>(Wq, Wk, Wv, Wskip, out);
    attn_kernel<<<dim3(16, NP), 128, SMEM_ATTN>>>(out);
}

// round 15
// speedup vs baseline: 1.1022x; 1.0312x over previous
#include <cuda_runtime.h>
#include <cuda_bf16.h>
#include <cuda_fp16.h>
#include <cstdint>

#define NB   4
#define CIN  128
#define NTOT 2048
#define NH   4
#define HD   64
#define OUTC 256
#define NP   16
#define NCHUNK 32

// ---------------- scratch ----------------
__device__ __half g_x[NB * NTOT * CIN];                // scattered input fp16 (b,n,c)
__device__ __nv_bfloat16 g_ph[NB * NTOT * CIN];        // pcd_up hi (b,n,c)
__device__ __nv_bfloat16 g_pl[NB * NTOT * CIN];        // pcd_up lo
__device__ __half g_q[NP * NTOT * HD];                 // (p,n,d) fp16, pre-scaled log2e/8
__device__ __half g_k[NP * NTOT * HD];                 // (p,n,d) fp16
__device__ __half g_v[NP * NTOT * HD];                 // (p,n,d) fp16

// ---------------- helpers ----------------
__device__ __forceinline__ uint32_t smem_u32(const void* p) {
    uint32_t a;
    asm("{ .reg .u64 t; cvta.to.shared.u64 t, %1; cvt.u32.u64 %0, t; }" : "=r"(a) : "l"(p));
    return a;
}
__device__ __forceinline__ void ldsm_x4(uint32_t& r0, uint32_t& r1, uint32_t& r2, uint32_t& r3,
                                        uint32_t addr) {
    asm volatile("ldmatrix.sync.aligned.m8n8.x4.shared.b16 {%0,%1,%2,%3}, [%4];"
                 : "=r"(r0), "=r"(r1), "=r"(r2), "=r"(r3) : "r"(addr));
}
__device__ __forceinline__ void ldsm_x4_t(uint32_t& r0, uint32_t& r1, uint32_t& r2, uint32_t& r3,
                                          uint32_t addr) {
    asm volatile("ldmatrix.sync.aligned.m8n8.x4.trans.shared.b16 {%0,%1,%2,%3}, [%4];"
                 : "=r"(r0), "=r"(r1), "=r"(r2), "=r"(r3) : "r"(addr));
}
__device__ __forceinline__ void mma16816(float* d, const uint32_t* a, uint32_t b0, uint32_t b1) {
    asm volatile("mma.sync.aligned.m16n8k16.row.col.f32.bf16.bf16.f32 "
                 "{%0,%1,%2,%3}, {%4,%5,%6,%7}, {%8,%9}, {%0,%1,%2,%3};"
                 : "+f"(d[0]), "+f"(d[1]), "+f"(d[2]), "+f"(d[3])
                 : "r"(a[0]), "r"(a[1]), "r"(a[2]), "r"(a[3]), "r"(b0), "r"(b1));
}
__device__ __forceinline__ void mma16816h(float* d, const uint32_t* a, uint32_t b0, uint32_t b1) {
    asm volatile("mma.sync.aligned.m16n8k16.row.col.f32.f16.f16.f32 "
                 "{%0,%1,%2,%3}, {%4,%5,%6,%7}, {%8,%9}, {%0,%1,%2,%3};"
                 : "+f"(d[0]), "+f"(d[1]), "+f"(d[2]), "+f"(d[3])
                 : "r"(a[0]), "r"(a[1]), "r"(a[2]), "r"(a[3]), "r"(b0), "r"(b1));
}
#define CP16(dst, src) asm volatile("cp.async.cg.shared.global [%0], [%1], 16;" :: "r"(dst), "l"(src))
#define CP_COMMIT()    asm volatile("cp.async.commit_group;" ::: "memory")
#define CP_WAIT(n)     asm volatile("cp.async.wait_group %0;" :: "n"(n) : "memory")

__device__ __forceinline__ void split_bf16(float x, __nv_bfloat16& hi, __nv_bfloat16& lo) {
    hi = __float2bfloat16(x);
    lo = __float2bfloat16(x - __bfloat162float(hi));
}
__device__ __forceinline__ uint32_t hadd2u(uint32_t a, uint32_t b) {
    uint32_t r;
    asm("add.f16x2 %0, %1, %2;" : "=r"(r) : "r"(a), "r"(b));
    return r;
}
__device__ __forceinline__ float2 h2_to_f2(uint32_t h) {
    float2 f;
    asm("{ .reg .f16 lo, hi;\n\t mov.b32 {lo, hi}, %2;\n\t"
        "cvt.f32.f16 %0, lo;\n\t cvt.f32.f16 %1, hi; }"
        : "=f"(f.x), "=f"(f.y) : "r"(h));
    return f;
}

// ============================================================
// K1: tiled transpose + scatter
// ============================================================
__global__ __launch_bounds__(256) void prep_kernel(
    const float* __restrict__ sel, const float* __restrict__ drp,
    const int* __restrict__ isel, const int* __restrict__ idrp,
    const float* __restrict__ pcd)
{
    __shared__ float S[128][33];
    __shared__ int dsts[32];
    int tx = blockIdx.x, mode = blockIdx.y, b = blockIdx.z;
    int t = threadIdx.x;

    if (mode == 0) {
        const float* src; const int* ip; int n0;
        if (tx < 32) { src = sel + (size_t)b * CIN * 1024; ip = isel; n0 = tx * 32; }
        else         { src = drp + (size_t)b * CIN * 1024; ip = idrp; n0 = tx * 32 - 1024; }
        #pragma unroll
        for (int i = 0; i < 16; ++i) {
            int idx = t + i * 256;
            int c = idx >> 5, n = idx & 31;
            S[c][n] = src[(size_t)c * 1024 + n0 + n];
        }
        if (t < 32) dsts[t] = ip[b * 1024 + n0 + t];
    } else {
        int n0 = tx * 32;
        #pragma unroll
        for (int i = 0; i < 16; ++i) {
            int idx = t + i * 256;
            int c = idx >> 5, n = idx & 31;
            S[c][n] = pcd[((size_t)b * CIN + c) * NTOT + n0 + n];
        }
        if (t < 32) dsts[t] = n0 + t;
    }
    __syncthreads();

    int n = t >> 3, cs = (t & 7) * 16;
    int dst = dsts[n];
    if (mode == 0) {
        __half* dx = g_x + ((size_t)(b * NTOT + dst)) * CIN + cs;
        __align__(16) __half hb[16];
        #pragma unroll
        for (int i = 0; i < 16; ++i) hb[i] = __float2half_rn(S[cs + i][n]);
        *(uint4*)dx       = *(uint4*)hb;
        *(uint4*)(dx + 8) = *(uint4*)(hb + 8);
    } else {
        __nv_bfloat16* dh = g_ph + ((size_t)(b * NTOT + dst)) * CIN + cs;
        __nv_bfloat16* dl = g_pl + ((size_t)(b * NTOT + dst)) * CIN + cs;
        __align__(16) __nv_bfloat16 hb[16], lb[16];
        #pragma unroll
        for (int i = 0; i < 16; ++i) split_bf16(S[cs + i][n], hb[i], lb[i]);
        *(uint4*)dh       = *(uint4*)hb;
        *(uint4*)(dh + 8) = *(uint4*)(hb + 8);
        *(uint4*)dl       = *(uint4*)lb;
        *(uint4*)(dl + 8) = *(uint4*)(lb + 8);
    }
}

// ============================================================
// K2: projections on tensor cores
//     ob<4: q+k+v fused for head ob (fp16, X loaded once)
//     ob>=4: skip head ob-4 (3-term bf16)
// ============================================================
#define PQW 0            // 3 x 17408 W tiles (q,k,v)
#define PQX 52224        // X fp16 tile
#define PQS 87040        // staging 18432
#define PWH 0
#define PWL 17408
#define PXH 34816
#define PXL 69632
#define SMEM_PROJ 105472

__global__ __launch_bounds__(256, 2) void proj_kernel(
    const float* __restrict__ Wq, const float* __restrict__ Wk,
    const float* __restrict__ Wv, const float* __restrict__ Wskip,
    float* __restrict__ out)
{
    extern __shared__ __align__(1024) char smem[];
    uint32_t sb = smem_u32(smem);
    int tid = threadIdx.x, wid = tid >> 5, lane = tid & 31;
    int nb = blockIdx.x, ob = blockIdx.y, b = blockIdx.z;
    int mw = wid & 3, nw = wid >> 2;

    if (ob < 4) {
        // ================= fused q/k/v for head h =================
        int h = ob;
        int p = b * NH + h;
        const float* Wm[3] = { Wq + h * 64 * CIN, Wk + h * 64 * CIN, Wv + h * 64 * CIN };
        const __half* X = g_x + ((size_t)b * NTOT + nb * 128) * CIN;

        #pragma unroll
        for (int l = 0; l < 24; ++l) {
            int idx = tid + l * 256;               // 6144 float4
            int mm = idx >> 11;
            int i2 = idx & 2047;
            int o = i2 >> 5, c4 = (i2 & 31) * 4;
            float4 w = *(const float4*)(Wm[mm] + o * 128 + c4);
            __align__(8) __half hw[4] = {
                __float2half_rn(w.x), __float2half_rn(w.y),
                __float2half_rn(w.z), __float2half_rn(w.w) };
            *(uint2*)(smem + PQW + mm * 17408 + o * 272 + c4 * 2) = *(uint2*)hw;
        }
        #pragma unroll
        for (int l = 0; l < 8; ++l) {
            int idx = tid + l * 256;               // 2048 uint4
            int n = idx >> 4, u = idx & 15;
            *(uint4*)(smem + PQX + n * 272 + u * 16) = ((const uint4*)(X + (size_t)n * CIN))[u];
        }
        __syncthreads();

        uint32_t wa_rel = (mw * 16 + (lane & 15)) * 272 + (lane >> 4) * 16;
        uint32_t xb = sb + PQX + (((lane & 7) | ((lane & 16) >> 1)) + nw * 64) * 272
                    + ((lane >> 3) & 1) * 16;
        float acc[3][8][4] = {};

        #pragma unroll
        for (int kt = 0; kt < 8; ++kt) {
            uint32_t ah[3][4];
            #pragma unroll
            for (int mm = 0; mm < 3; ++mm)
                ldsm_x4(ah[mm][0], ah[mm][1], ah[mm][2], ah[mm][3],
                        sb + PQW + mm * 17408 + wa_rel + kt * 32);
            #pragma unroll
            for (int nt = 0; nt < 4; ++nt) {
                uint32_t bh[4];
                ldsm_x4(bh[0], bh[1], bh[2], bh[3], xb + nt * (16 * 272) + kt * 32);
                #pragma unroll
                for (int mm = 0; mm < 3; ++mm) {
                    mma16816h(acc[mm][2 * nt],     ah[mm], bh[0], bh[1]);
                    mma16816h(acc[mm][2 * nt + 1], ah[mm], bh[2], bh[3]);
                }
            }
        }

        // ---- epilogues: stage [n][d] fp16 (pitch 144B), copy to (p,n,d) ----
        __half* S = (__half*)(smem + PQS);
        #pragma unroll
        for (int mm = 0; mm < 3; ++mm) {
            // q pre-scale folds 1/sqrt(64)=1/8 AND log2(e) so attn S is log2-domain
            float scale = (mm == 0) ? 0.125f * 1.44269504f : 1.0f;
            __syncthreads();
            #pragma unroll
            for (int g = 0; g < 8; ++g) {
                int n0 = nw * 64 + g * 8 + (lane & 3) * 2;
                #pragma unroll
                for (int cc = 0; cc < 2; ++cc) {
                    int d = mw * 16 + (lane >> 2) + cc * 8;
                    #pragma unroll
                    for (int e = 0; e < 2; ++e)
                        S[(n0 + e) * 72 + d] = __float2half_rn(acc[mm][g][2 * cc + e] * scale);
                }
            }
            __syncthreads();
            __half* dst = (mm == 0 ? g_q : mm == 1 ? g_k : g_v)
                        + ((size_t)p * NTOT + nb * 128) * HD;
            #pragma unroll
            for (int l = 0; l < 4; ++l) {
                int idx = tid + l * 256;           // 1024 uint4
                int n = idx >> 3, u = idx & 7;
                ((uint4*)dst)[idx] = *(const uint4*)((char*)S + n * 144 + u * 16);
            }
        }
    } else {
        // ================= skip head (3-term bf16) =================
        int h = ob - 4;
        const float* W = Wskip + h * 64 * CIN;
        const __nv_bfloat16* Xh = g_ph + ((size_t)b * NTOT + nb * 128) * CIN;
        const __nv_bfloat16* Xl = g_pl + ((size_t)b * NTOT + nb * 128) * CIN;

        #pragma unroll
        for (int l = 0; l < 8; ++l) {
            int idx = tid + l * 256;               // 2048 float4
            int o = idx >> 5, c4 = (idx & 31) * 4;
            float4 w = *(const float4*)(W + o * 128 + c4);
            __nv_bfloat16 h0, h1, h2, h3, l0, l1, l2, l3;
            split_bf16(w.x, h0, l0); split_bf16(w.y, h1, l1);
            split_bf16(w.z, h2, l2); split_bf16(w.w, h3, l3);
            __nv_bfloat162* dh = (__nv_bfloat162*)(smem + PWH + o * 272 + c4 * 2);
            __nv_bfloat162* dl = (__nv_bfloat162*)(smem + PWL + o * 272 + c4 * 2);
            dh[0] = {h0, h1}; dh[1] = {h2, h3};
            dl[0] = {l0, l1}; dl[1] = {l2, l3};
        }
        #pragma unroll
        for (int l = 0; l < 8; ++l) {
            int idx = tid + l * 256;               // 2048 uint4
            int n = idx >> 4, u = idx & 15;
            *(uint4*)(smem + PXH + n * 272 + u * 16) = ((const uint4*)(Xh + (size_t)n * CIN))[u];
            *(uint4*)(smem + PXL + n * 272 + u * 16) = ((const uint4*)(Xl + (size_t)n * CIN))[u];
        }
        __syncthreads();

        uint32_t wa = sb + PWH + (mw * 16 + (lane & 15)) * 272 + (lane >> 4) * 16;
        uint32_t xb = sb + PXH + (((lane & 7) | ((lane & 16) >> 1)) + nw * 64) * 272
                    + ((lane >> 3) & 1) * 16;
        float acc[8][4] = {};

        #pragma unroll
        for (int kt = 0; kt < 8; ++kt) {
            uint32_t ah[4], al[4];
            ldsm_x4(ah[0], ah[1], ah[2], ah[3], wa + kt * 32);
            ldsm_x4(al[0], al[1], al[2], al[3], wa + (PWL - PWH) + kt * 32);
            #pragma unroll
            for (int nt = 0; nt < 4; ++nt) {
                uint32_t bh[4], bl[4];
                uint32_t base = xb + nt * (16 * 272) + kt * 32;
                ldsm_x4(bh[0], bh[1], bh[2], bh[3], base);
                ldsm_x4(bl[0], bl[1], bl[2], bl[3], base + (PXL - PXH));
                mma16816(acc[2 * nt],     ah, bh[0], bh[1]);
                mma16816(acc[2 * nt + 1], ah, bh[2], bh[3]);
                mma16816(acc[2 * nt],     al, bh[0], bh[1]);
                mma16816(acc[2 * nt + 1], al, bh[2], bh[3]);
                mma16816(acc[2 * nt],     ah, bl[0], bl[1]);
                mma16816(acc[2 * nt + 1], ah, bl[2], bl[3]);
            }
        }

        #pragma unroll
        for (int g = 0; g < 8; ++g) {
            int n_g = nb * 128 + nw * 64 + g * 8 + (lane & 3) * 2;
            #pragma unroll
            for (int cc = 0; cc < 2; ++cc) {
                int o_g = h * 64 + mw * 16 + (lane >> 2) + cc * 8;
                float2 st = {acc[g][2 * cc], acc[g][2 * cc + 1]};
                *(float2*)(out + ((size_t)(b * OUTC + o_g)) * NTOT + n_g) = st;
            }
        }
    }
}

// ============================================================
// K3: fused flash attention, single-term fp16 HMMA, f16x2 ex2
//     4 warps x M=32 = 128 rows/CTA, 2 CTAs/SM, grid (16 it, 16 p)
// ============================================================
#define PIT 144
#define AQ  0
#define AK0 18432
#define AK1 27648
#define AV0 36864
#define AV1 46080
#define SMEM_ATTN 55296

__device__ __forceinline__ void load_kv(uint32_t sb, int p, int c, int s, int tid) {
    const char* gk = (const char*)(g_k + ((size_t)p * NTOT + c * 64) * HD);
    const char* gv = (const char*)(g_v + ((size_t)p * NTOT + c * 64) * HD);
    uint32_t kd = sb + (s ? AK1 : AK0);
    uint32_t vd = sb + (s ? AV1 : AV0);
    #pragma unroll
    for (int l = 0; l < 4; ++l) {
        int idx = tid + l * 128;                   // 512 x 16B each
        int row = idx >> 3, c16 = (idx & 7) * 16;
        CP16(kd + row * PIT + c16, gk + row * 128 + c16);
        CP16(vd + row * PIT + c16, gv + row * 128 + c16);
    }
}

__global__ __launch_bounds__(128, 2) void attn_kernel(float* __restrict__ out)
{
    extern __shared__ __align__(1024) char smem[];
    uint32_t sb = smem_u32(smem);
    int tid = threadIdx.x, wid = tid >> 5, lane = tid & 31;
    int g = lane >> 2, t = lane & 3;
    int it = blockIdx.x, p = blockIdx.y;
    int b = p >> 2, h = p & 3;

    // ---- issue Q (128 rows x 128B) + chunk0 as group 0 ----
    {
        const char* gq = (const char*)(g_q + ((size_t)p * NTOT + it * 128) * HD);
        #pragma unroll
        for (int l = 0; l < 8; ++l) {
            int idx = tid + l * 128;               // 1024 x 16B
            int row = idx >> 3, c16 = (idx & 7) * 16;
            CP16(sb + AQ + row * PIT + c16, gq + row * 128 + c16);
        }
        load_kv(sb, p, 0, 0, tid);
        CP_COMMIT();
    }

    uint32_t qa = sb + AQ + (wid * 32 + (lane & 15)) * PIT + (lane >> 4) * 16;
    uint32_t kb_rel = ((lane & 7) | ((lane & 16) >> 1)) * PIT + ((lane >> 3) & 1) * 16;
    uint32_t vb_rel = (lane & 15) * PIT + (lane >> 4) * 16;

    float o[2][8][4] = {};
    float rs[2][2] = {};

    for (int c = 0; c < NCHUNK; ++c) {
        if (c) __syncthreads();
        if (c < NCHUNK - 1) {
            load_kv(sb, p, c + 1, (c + 1) & 1, tid);
            CP_COMMIT();
            CP_WAIT(1);
        } else {
            CP_WAIT(0);
        }
        __syncthreads();

        uint32_t kb = sb + ((c & 1) ? AK1 : AK0) + kb_rel;
        uint32_t vb = sb + ((c & 1) ? AV1 : AV0) + vb_rel;

        // ---- S = Q Kᵀ (single-term fp16; S already log2-domain) ----
        float s[2][8][4] = {};
        #pragma unroll
        for (int kt = 0; kt < 4; ++kt) {
            uint32_t aq[2][4];
            #pragma unroll
            for (int mi = 0; mi < 2; ++mi)
                ldsm_x4(aq[mi][0], aq[mi][1], aq[mi][2], aq[mi][3],
                        qa + mi * (16 * PIT) + kt * 32);
            #pragma unroll
            for (int nt2 = 0; nt2 < 4; ++nt2) {
                uint32_t bh[4];
                ldsm_x4(bh[0], bh[1], bh[2], bh[3], kb + nt2 * (16 * PIT) + kt * 32);
                #pragma unroll
                for (int mi = 0; mi < 2; ++mi) {
                    mma16816h(s[mi][2 * nt2],     aq[mi], bh[0], bh[1]);
                    mma16816h(s[mi][2 * nt2 + 1], aq[mi], bh[2], bh[3]);
                }
            }
        }

        // ---- per-kt: cvt->f16x2, ex2.f16x2, P·V; half2 rowsum per chunk ----
        uint32_t hs[2][2] = {{0u, 0u}, {0u, 0u}};
        #pragma unroll
        for (int kt = 0; kt < 4; ++kt) {
            uint32_t ph[2][4];
            #pragma unroll
            for (int mi = 0; mi < 2; ++mi) {
                #pragma unroll
                for (int hf = 0; hf < 2; ++hf) {
                    float* sv = s[mi][2 * kt + hf];
                    uint32_t a01, a23, p01, p23;
                    asm("cvt.rn.f16x2.f32 %0, %1, %2;" : "=r"(a01) : "f"(sv[1]), "f"(sv[0]));
                    asm("cvt.rn.f16x2.f32 %0, %1, %2;" : "=r"(a23) : "f"(sv[3]), "f"(sv[2]));
                    asm("ex2.approx.f16x2 %0, %1;" : "=r"(p01) : "r"(a01));
                    asm("ex2.approx.f16x2 %0, %1;" : "=r"(p23) : "r"(a23));
                    ph[mi][2 * hf]     = p01;
                    ph[mi][2 * hf + 1] = p23;
                    hs[mi][0] = hadd2u(hs[mi][0], p01);   // row r    (2 j-cols)
                    hs[mi][1] = hadd2u(hs[mi][1], p23);   // row r+8  (2 j-cols)
                }
            }
            #pragma unroll
            for (int nt2 = 0; nt2 < 4; ++nt2) {
                uint32_t bh[4];
                ldsm_x4_t(bh[0], bh[1], bh[2], bh[3], vb + kt * (16 * PIT) + nt2 * 32);
                #pragma unroll
                for (int mi = 0; mi < 2; ++mi) {
                    mma16816h(o[mi][2 * nt2],     ph[mi], bh[0], bh[1]);
                    mma16816h(o[mi][2 * nt2 + 1], ph[mi], bh[2], bh[3]);
                }
            }
        }
        // per-chunk: fold half2 partial sums into fp32 accumulators
        #pragma unroll
        for (int mi = 0; mi < 2; ++mi) {
            float2 f0 = h2_to_f2(hs[mi][0]);
            float2 f1 = h2_to_f2(hs[mi][1]);
            rs[mi][0] += f0.x + f0.y;
            rs[mi][1] += f1.x + f1.y;
        }
    }

    // ---- rowsum reduce across quad, normalize, transpose via smem ----
    float inv[2][2];
    #pragma unroll
    for (int mi = 0; mi < 2; ++mi) {
        #pragma unroll
        for (int cc = 0; cc < 2; ++cc) {
            float v = rs[mi][cc];
            v += __shfl_xor_sync(0xffffffffu, v, 1);
            v += __shfl_xor_sync(0xffffffffu, v, 2);
            inv[mi][cc] = 1.0f / v;
        }
    }

    __syncthreads();
    float* Os = (float*)smem;                      // [64][129]
    #pragma unroll
    for (int mi = 0; mi < 2; ++mi) {
        int i0 = wid * 32 + mi * 16 + g;
        #pragma unroll
        for (int dt = 0; dt < 8; ++dt) {
            int d0 = dt * 8 + t * 2;
            Os[d0 * 129 + i0]           = o[mi][dt][0] * inv[mi][0];
            Os[(d0 + 1) * 129 + i0]     = o[mi][dt][1] * inv[mi][0];
            Os[d0 * 129 + i0 + 8]       = o[mi][dt][2] * inv[mi][1];
            Os[(d0 + 1) * 129 + i0 + 8] = o[mi][dt][3] * inv[mi][1];
        }
    }
    __syncthreads();

    #pragma unroll
    for (int l = 0; l < 64; ++l) {
        int idx = tid + l * 128;                   // 8192 elements
        int i = idx & 127, d = idx >> 7;
        size_t go = ((size_t)(b * OUTC + h * HD + d)) * NTOT + it * 128 + i;
        out[go] += Os[d * 129 + i];
    }
}

// ============================================================
extern "C" void kernel_launch(void* const* d_in, const int* in_sizes, int n_in,
                              void* d_out, int out_size)
{
    const float* pcd   = (const float*)d_in[0];
    const float* sel   = (const float*)d_in[1];
    const float* drp   = (const float*)d_in[2];
    const int*   isel  = (const int*)d_in[3];
    const int*   idrp  = (const int*)d_in[4];
    const float* Wq    = (const float*)d_in[5];
    const float* Wk    = (const float*)d_in[6];
    const float* Wv    = (const float*)d_in[7];
    const float* Wskip = (const float*)d_in[8];
    float* out = (float*)d_out;

    cudaFuncSetAttribute(proj_kernel, cudaFuncAttributeMaxDynamicSharedMemorySize, SMEM_PROJ);
    cudaFuncSetAttribute(attn_kernel, cudaFuncAttributeMaxDynamicSharedMemorySize, SMEM_ATTN);

    prep_kernel<<<dim3(64, 2, NB), 256>>>(sel, drp, isel, idrp, pcd);
    proj_kernel<<<dim3(16, 8, NB), 256, SMEM_PROJ>>>(Wq, Wk, Wv, Wskip, out);
    attn_kernel<<<dim3(16, NP), 128, SMEM_ATTN>>>(out);
}